// round 16
// baseline (speedup 1.0000x reference)
#include <cuda_runtime.h>
#include <cuda_bf16.h>

// Sparsemax, rows of N=2048 fp32. One 128-thread block (4 warps) per row,
// row register-resident (4 float4/lane). FINAL — measured session optimum,
// reproduced five times (ncu 151.0-153.6us; DRAM 83.6-85.1%; 6.6-6.75
// TB/s). 537MB in + 537MB out is the semantic-minimum traffic and this
// configuration runs at the chip's practical mixed r/w HBM ceiling: the
// kernel is bandwidth-floor-limited, not code-limited.
//
// Algorithm: sum_i relu(x_i - tau) = 1 bounds the max term by 1, so
// tau in [M-1, M) (M = row max) => support ⊆ {x > M-1} (~7 of 2048 for
// Gaussian rows). Per row:
//   1. block max M (shfl + 4-slot smem + 1 bar)
//   2. per-lane top-2 above M-1 published to smem (float2/thread, NEG-pad),
//      exact per-lane candidate count; 1 bar
//   3. all warps redundantly run the Newton fixed point
//         tau <- (sum_{x>tau} - 1)/count
//      from tau = M-1 (iter 1 reproduces (S-1)/C); 4x LDS.64/lane; exact
//      stop when the support count is stable (monotone from below; the max
//      element always survives). Degenerate rows (any lane >2 candidates):
//      exact block-wide fallback over the register-resident row.
//   4. output relu(x - tau) from registers, streaming stores.

constexpr int ROW_N   = 2048;
constexpr int THREADS = 128;
constexpr int NWARP   = THREADS / 32;        // 4
constexpr int F4PT    = ROW_N / 4 / THREADS; // 4

__global__ __launch_bounds__(THREADS, 12)
void sparsemax_kernel(const float* __restrict__ in, float* __restrict__ out) {
    __shared__ float  pm[NWARP];
    __shared__ float  ps[NWARP];
    __shared__ float  pc[NWARP];
    __shared__ float2 cand[THREADS];         // 256 slots, NEG-padded
    __shared__ int    sflag;

    const int t    = threadIdx.x;
    const int lane = t & 31;
    const int wid  = t >> 5;
    const size_t row = blockIdx.x;

    const float4* x4 = (const float4*)(in  + row * (size_t)ROW_N);
    float4*       y4 = (float4*)      (out + row * (size_t)ROW_N);

    // ---- load: 4 coalesced LDG.128 per lane, front-batched ----
    float4 a[F4PT];
#pragma unroll
    for (int i = 0; i < F4PT; i++) a[i] = __ldcs(&x4[t + THREADS * i]);

    // ---- block max ----
    float m = fmaxf(fmaxf(a[0].x, a[0].y), fmaxf(a[0].z, a[0].w));
#pragma unroll
    for (int i = 1; i < F4PT; i++)
        m = fmaxf(m, fmaxf(fmaxf(a[i].x, a[i].y), fmaxf(a[i].z, a[i].w)));
#pragma unroll
    for (int o = 16; o; o >>= 1)
        m = fmaxf(m, __shfl_xor_sync(0xffffffffu, m, o));
    if (lane == 0) pm[wid] = m;
    if (t == 0) sflag = 0;
    __syncthreads();                                       // bar 1

    float M = fmaxf(fmaxf(pm[0], pm[1]), fmaxf(pm[2], pm[3]));
    const float thr = M - 1.0f;

    // ---- per-lane top-2 insert + exact candidate count ----
    const float NEG = -3.0e38f;
    float c0 = NEG, c1 = NEG;
    int nc = 0;
#pragma unroll
    for (int i = 0; i < F4PT; i++) {
        float e[4] = {a[i].x, a[i].y, a[i].z, a[i].w};
#pragma unroll
        for (int j = 0; j < 4; j++) {
            float x = e[j];
            nc += (x > thr);                 // independent of the chain below
            float t0 = fminf(c0, x);
            c0 = fmaxf(c0, x);
            c1 = fmaxf(c1, t0);
        }
    }
    float2 q;
    q.x = (c0 > thr) ? c0 : NEG;
    q.y = (c1 > thr) ? c1 : NEG;
    cand[t] = q;                             // one STS.64
    if (__ballot_sync(0xffffffffu, nc > 2)) sflag = 1;     // benign race
    __syncthreads();                                       // bar 2

    float tau;
    if (sflag == 0) {
        // ---- fast path: every warp runs the same tiny Newton (no bar) ----
        tau = thr;                           // iter 1 yields (S-1)/C exactly
        int kprev = -1;
        for (int iter = 0; iter < 40; ++iter) {
            float s2 = 0.f, c2 = 0.f;
#pragma unroll
            for (int j = 0; j < 4; j++) {    // 4x LDS.64 per lane
                float2 w = cand[lane + 32 * j];
                if (w.x > tau) { s2 += w.x; c2 += 1.f; }
                if (w.y > tau) { s2 += w.y; c2 += 1.f; }
            }
#pragma unroll
            for (int o = 16; o; o >>= 1) {
                s2 += __shfl_xor_sync(0xffffffffu, s2, o);
                c2 += __shfl_xor_sync(0xffffffffu, c2, o);
            }
            int k2 = (int)c2;                // max element always survives
            tau = (s2 - 1.0f) / c2;
            if (k2 == kprev) break;          // support stable -> exact
            kprev = k2;
        }
    } else {
        // ---- exact fallback (degenerate rows): block-wide Newton over regs ----
        tau = thr;
        int kprev = -1;
        for (int iter = 0; iter < 64; ++iter) {
            float s2 = 0.f, c2 = 0.f;
#pragma unroll
            for (int i = 0; i < F4PT; i++) {
                if (a[i].x > tau) { s2 += a[i].x; c2 += 1.f; }
                if (a[i].y > tau) { s2 += a[i].y; c2 += 1.f; }
                if (a[i].z > tau) { s2 += a[i].z; c2 += 1.f; }
                if (a[i].w > tau) { s2 += a[i].w; c2 += 1.f; }
            }
#pragma unroll
            for (int o = 16; o; o >>= 1) {
                s2 += __shfl_xor_sync(0xffffffffu, s2, o);
                c2 += __shfl_xor_sync(0xffffffffu, c2, o);
            }
            if (lane == 0) { ps[wid] = s2; pc[wid] = c2; }
            __syncthreads();
            float S2 = ps[0] + ps[1] + ps[2] + ps[3];
            float C2 = pc[0] + pc[1] + pc[2] + pc[3];
            int k2 = (int)C2;
            tau = (S2 - 1.0f) / C2;
            __syncthreads();                 // ps/pc reusable next iter
            if (k2 == kprev) break;
            kprev = k2;
        }
    }

    // ---- output: relu(x - tau) from registers ----
#pragma unroll
    for (int i = 0; i < F4PT; i++) {
        float4 o;
        o.x = fmaxf(a[i].x - tau, 0.f);
        o.y = fmaxf(a[i].y - tau, 0.f);
        o.z = fmaxf(a[i].z - tau, 0.f);
        o.w = fmaxf(a[i].w - tau, 0.f);
        __stcs(&y4[t + THREADS * i], o);
    }
}

extern "C" void kernel_launch(void* const* d_in, const int* in_sizes, int n_in,
                              void* d_out, int out_size) {
    const float* in = (const float*)d_in[0];
    float* out = (float*)d_out;
    int rows = in_sizes[0] / ROW_N;          // 65536
    sparsemax_kernel<<<rows, THREADS>>>(in, out);
}

// round 17
// speedup vs baseline: 1.0012x; 1.0012x over previous
#include <cuda_runtime.h>
#include <cuda_bf16.h>

// Sparsemax, rows of N=2048 fp32. One 128-thread block (4 warps) per row,
// row register-resident (4 float4/lane). FINAL — measured session optimum,
// reproduced six times (ncu 150.9-153.6us; DRAM 83.6-85.1%; ~6.7 TB/s).
// 537MB in + 537MB out is the semantic-minimum traffic and this
// configuration runs at the chip's practical mixed r/w HBM ceiling: the
// kernel is bandwidth-floor-limited, not code-limited.
//
// Algorithm: sum_i relu(x_i - tau) = 1 bounds the max term by 1, so
// tau in [M-1, M) (M = row max) => support ⊆ {x > M-1} (~7 of 2048 for
// Gaussian rows). Per row:
//   1. block max M (shfl + 4-slot smem + 1 bar)
//   2. per-lane top-2 above M-1 published to smem (float2/thread, NEG-pad),
//      exact per-lane candidate count; 1 bar
//   3. all warps redundantly run the Newton fixed point
//         tau <- (sum_{x>tau} - 1)/count
//      from tau = M-1 (iter 1 reproduces (S-1)/C); 4x LDS.64/lane; exact
//      stop when the support count is stable (monotone from below; the max
//      element always survives). Degenerate rows (any lane >2 candidates):
//      exact block-wide fallback over the register-resident row.
//   4. output relu(x - tau) from registers, streaming stores.

constexpr int ROW_N   = 2048;
constexpr int THREADS = 128;
constexpr int NWARP   = THREADS / 32;        // 4
constexpr int F4PT    = ROW_N / 4 / THREADS; // 4

__global__ __launch_bounds__(THREADS, 12)
void sparsemax_kernel(const float* __restrict__ in, float* __restrict__ out) {
    __shared__ float  pm[NWARP];
    __shared__ float  ps[NWARP];
    __shared__ float  pc[NWARP];
    __shared__ float2 cand[THREADS];         // 256 slots, NEG-padded
    __shared__ int    sflag;

    const int t    = threadIdx.x;
    const int lane = t & 31;
    const int wid  = t >> 5;
    const size_t row = blockIdx.x;

    const float4* x4 = (const float4*)(in  + row * (size_t)ROW_N);
    float4*       y4 = (float4*)      (out + row * (size_t)ROW_N);

    // ---- load: 4 coalesced LDG.128 per lane, front-batched ----
    float4 a[F4PT];
#pragma unroll
    for (int i = 0; i < F4PT; i++) a[i] = __ldcs(&x4[t + THREADS * i]);

    // ---- block max ----
    float m = fmaxf(fmaxf(a[0].x, a[0].y), fmaxf(a[0].z, a[0].w));
#pragma unroll
    for (int i = 1; i < F4PT; i++)
        m = fmaxf(m, fmaxf(fmaxf(a[i].x, a[i].y), fmaxf(a[i].z, a[i].w)));
#pragma unroll
    for (int o = 16; o; o >>= 1)
        m = fmaxf(m, __shfl_xor_sync(0xffffffffu, m, o));
    if (lane == 0) pm[wid] = m;
    if (t == 0) sflag = 0;
    __syncthreads();                                       // bar 1

    float M = fmaxf(fmaxf(pm[0], pm[1]), fmaxf(pm[2], pm[3]));
    const float thr = M - 1.0f;

    // ---- per-lane top-2 insert + exact candidate count ----
    const float NEG = -3.0e38f;
    float c0 = NEG, c1 = NEG;
    int nc = 0;
#pragma unroll
    for (int i = 0; i < F4PT; i++) {
        float e[4] = {a[i].x, a[i].y, a[i].z, a[i].w};
#pragma unroll
        for (int j = 0; j < 4; j++) {
            float x = e[j];
            nc += (x > thr);                 // independent of the chain below
            float t0 = fminf(c0, x);
            c0 = fmaxf(c0, x);
            c1 = fmaxf(c1, t0);
        }
    }
    float2 q;
    q.x = (c0 > thr) ? c0 : NEG;
    q.y = (c1 > thr) ? c1 : NEG;
    cand[t] = q;                             // one STS.64
    if (__ballot_sync(0xffffffffu, nc > 2)) sflag = 1;     // benign race
    __syncthreads();                                       // bar 2

    float tau;
    if (sflag == 0) {
        // ---- fast path: every warp runs the same tiny Newton (no bar) ----
        tau = thr;                           // iter 1 yields (S-1)/C exactly
        int kprev = -1;
        for (int iter = 0; iter < 40; ++iter) {
            float s2 = 0.f, c2 = 0.f;
#pragma unroll
            for (int j = 0; j < 4; j++) {    // 4x LDS.64 per lane
                float2 w = cand[lane + 32 * j];
                if (w.x > tau) { s2 += w.x; c2 += 1.f; }
                if (w.y > tau) { s2 += w.y; c2 += 1.f; }
            }
#pragma unroll
            for (int o = 16; o; o >>= 1) {
                s2 += __shfl_xor_sync(0xffffffffu, s2, o);
                c2 += __shfl_xor_sync(0xffffffffu, c2, o);
            }
            int k2 = (int)c2;                // max element always survives
            tau = (s2 - 1.0f) / c2;
            if (k2 == kprev) break;          // support stable -> exact
            kprev = k2;
        }
    } else {
        // ---- exact fallback (degenerate rows): block-wide Newton over regs ----
        tau = thr;
        int kprev = -1;
        for (int iter = 0; iter < 64; ++iter) {
            float s2 = 0.f, c2 = 0.f;
#pragma unroll
            for (int i = 0; i < F4PT; i++) {
                if (a[i].x > tau) { s2 += a[i].x; c2 += 1.f; }
                if (a[i].y > tau) { s2 += a[i].y; c2 += 1.f; }
                if (a[i].z > tau) { s2 += a[i].z; c2 += 1.f; }
                if (a[i].w > tau) { s2 += a[i].w; c2 += 1.f; }
            }
#pragma unroll
            for (int o = 16; o; o >>= 1) {
                s2 += __shfl_xor_sync(0xffffffffu, s2, o);
                c2 += __shfl_xor_sync(0xffffffffu, c2, o);
            }
            if (lane == 0) { ps[wid] = s2; pc[wid] = c2; }
            __syncthreads();
            float S2 = ps[0] + ps[1] + ps[2] + ps[3];
            float C2 = pc[0] + pc[1] + pc[2] + pc[3];
            int k2 = (int)C2;
            tau = (S2 - 1.0f) / C2;
            __syncthreads();                 // ps/pc reusable next iter
            if (k2 == kprev) break;
            kprev = k2;
        }
    }

    // ---- output: relu(x - tau) from registers ----
#pragma unroll
    for (int i = 0; i < F4PT; i++) {
        float4 o;
        o.x = fmaxf(a[i].x - tau, 0.f);
        o.y = fmaxf(a[i].y - tau, 0.f);
        o.z = fmaxf(a[i].z - tau, 0.f);
        o.w = fmaxf(a[i].w - tau, 0.f);
        __stcs(&y4[t + THREADS * i], o);
    }
}

extern "C" void kernel_launch(void* const* d_in, const int* in_sizes, int n_in,
                              void* d_out, int out_size) {
    const float* in = (const float*)d_in[0];
    float* out = (float*)d_out;
    int rows = in_sizes[0] / ROW_N;          // 65536
    sparsemax_kernel<<<rows, THREADS>>>(in, out);
}